// round 6
// baseline (speedup 1.0000x reference)
#include <cuda_runtime.h>
#include <cstdint>

// ---------------------------------------------------------------------------
// Warp-specialized tf32 mma.sync kernel (family-portable sm_103 PTX).
// Producer warps 0-7: GEMM1 (u@b chunk) + epilogue (x_new = T1 + decay*x).
// Consumer warps 8-15: GEMM2 (Out += x_new @ c chunk), one chunk behind,
// handshaking over a single x_new SMEM stage via named counting barriers.
// R6: merged prep kernel, L2 prefetch of X ahead of the epilogue, streaming
// cache hints on write-once stores / read-once loads.
// ---------------------------------------------------------------------------

static constexpr int BATCH = 65536;
static constexpr int DH = 512;
static constexpr int DI = 128;
static constexpr int DO = 128;
static constexpr int BM = 128;
static constexpr int NT = 512;    // 16 warps: 8 producer + 8 consumer
static constexpr int NCH = 8;     // h-chunks of 64

// SMEM float offsets (231424 B total)
static constexpr int U_OFF  = 0;      // u tile [128m x 128k] tf32 (64KB)
static constexpr int B_OFF0 = 16384;  // b chunk [128k x 64n] (32KB)
static constexpr int B_OFF1 = 24576;
static constexpr int C_OFF0 = 32768;  // c chunk [64k x 128n] (32KB)
static constexpr int C_OFF1 = 40960;
static constexpr int XN_OFF = 49152;  // x_new stage [128m x 64k] (32KB)
static constexpr int DEC_OFF = 57344; // decay[512] fp32
static constexpr int SMEM_BYTES = 57856 * 4;

__device__ float g_decay[512];
__device__ float g_bt[65536];   // tf32 bits, preswizzled [8ch][128k x 64n]
__device__ float g_ct[65536];   // tf32 bits, preswizzled [8ch][64k x 128n]

__device__ __forceinline__ uint32_t f2tf(float f) {
    uint32_t r;
    asm("cvt.rna.tf32.f32 %0, %1;" : "=r"(r) : "f"(f));
    return r;
}
__device__ __forceinline__ uint32_t smem_u32(const void* p) {
    uint32_t a;
    asm("{ .reg .u64 t; cvta.to.shared.u64 t, %1; cvt.u32.u64 %0, t; }" : "=r"(a) : "l"(p));
    return a;
}
__device__ __forceinline__ void cpa16(uint32_t d, const void* s) {
    asm volatile("cp.async.cg.shared.global [%0], [%1], 16;" :: "r"(d), "l"(s));
}
__device__ __forceinline__ void pref_l2(const void* p) {
    asm volatile("prefetch.global.L2 [%0];" :: "l"(p));
}
__device__ __forceinline__ float2 ldg_cs64(const float* p) {
    float2 v;
    asm volatile("ld.global.cs.v2.f32 {%0,%1}, [%2];" : "=f"(v.x), "=f"(v.y) : "l"(p));
    return v;
}
__device__ __forceinline__ void stg_cs64(float* p, float2 v) {
    asm volatile("st.global.cs.v2.f32 [%0], {%1,%2};" :: "l"(p), "f"(v.x), "f"(v.y));
}
#define CP_COMMIT() asm volatile("cp.async.commit_group;" ::: "memory")
#define CP_WAIT(n)  asm volatile("cp.async.wait_group %0;" :: "n"(n) : "memory")
#define BAR_SYNC(id, cnt) asm volatile("bar.sync %0, %1;" :: "n"(id), "n"(cnt) : "memory")
#define BAR_ARRIVE(id, cnt) asm volatile("bar.arrive %0, %1;" :: "n"(id), "n"(cnt) : "memory")
// ids: 1 = producer-internal, 2 = consumer-internal, 3 = xn full, 4 = xn empty

__device__ __forceinline__ void mma8(float* c, const uint32_t* a, uint32_t b0, uint32_t b1) {
    asm volatile(
        "mma.sync.aligned.m16n8k8.row.col.f32.tf32.tf32.f32 "
        "{%0,%1,%2,%3}, {%4,%5,%6,%7}, {%8,%9}, {%0,%1,%2,%3};"
        : "+f"(c[0]), "+f"(c[1]), "+f"(c[2]), "+f"(c[3])
        : "r"(a[0]), "r"(a[1]), "r"(a[2]), "r"(a[3]), "r"(b0), "r"(b1));
}

// ---------------- merged prep kernel (one launch, ~6us) ----------------
// 64 blocks x 512 threads. Threads 0-255 of every block swizzle b/c; block 0
// additionally computes softmax(a) with all 512 threads afterwards.
__global__ void prep_all(const float* __restrict__ A, const float* __restrict__ B,
                         const float* __restrict__ C) {
    __shared__ float red[512];
    const int t = threadIdx.x;
    if (t < 256) {
        int i = blockIdx.x * 256 + t;  // [0, 16384) float4 units
        int ch = i >> 11, rem = i & 2047;
        {
            int k = rem >> 4, j = rem & 15;
            float4 v = *(const float4*)(B + (size_t)k * DH + ch * 64 + 4 * j);
            int d = ch * 8192 + k * 64 + ((j ^ ((k & 3) << 1)) << 2);
            *(uint4*)&g_bt[d] = make_uint4(f2tf(v.x), f2tf(v.y), f2tf(v.z), f2tf(v.w));
        }
        {
            int h = rem >> 5, j = rem & 31;
            float4 v = *(const float4*)(C + (size_t)(ch * 64 + h) * DO + 4 * j);
            int d = ch * 8192 + h * 128 + ((j ^ ((h & 3) << 1)) << 2);
            *(uint4*)&g_ct[d] = make_uint4(f2tf(v.x), f2tf(v.y), f2tf(v.z), f2tf(v.w));
        }
    }
    if (blockIdx.x == 0) {
        float a = A[t];
        red[t] = a;
        __syncthreads();
        for (int o = 256; o > 0; o >>= 1) {
            if (t < o) red[t] = fmaxf(red[t], red[t + o]);
            __syncthreads();
        }
        float mx = red[0];
        __syncthreads();
        float e = expf(a - mx);
        red[t] = e;
        __syncthreads();
        for (int o = 256; o > 0; o >>= 1) {
            if (t < o) red[t] += red[t + o];
            __syncthreads();
        }
        g_decay[t] = e / red[0];
    }
}

// ------------------------------- main kernel -------------------------------
__global__ void __launch_bounds__(NT, 1)
rnn_kernel(const float* __restrict__ X, const float* __restrict__ U,
           float* __restrict__ OUT) {
    extern __shared__ float sm[];
    const int tid = threadIdx.x, wid = tid >> 5, lid = tid & 31;
    const int q = lid & 3, r = lid >> 2;
    const int row0 = (int)blockIdx.x * BM;
    const uint32_t smb = smem_u32(sm);

    if (wid < 8) {
        // ===================== PRODUCER (warps 0-7) =====================
        const int pt = tid;  // 0-255
        const int mb1 = (wid >> 1) * 32, nb1 = (wid & 1) * 32;  // GEMM1 tile 32x32

        // prologue: U + decay + b0 (group), b1 (group)
        {
            const float* ug = U + (size_t)row0 * DI;
            #pragma unroll
            for (int it = 0; it < 16; ++it) {
                int i = it * 256 + pt;
                int m = i >> 5, j = i & 31;
                uint32_t dst = smb + (uint32_t)(U_OFF + m * 128 + ((j ^ (m & 7)) << 2)) * 4u;
                cpa16(dst, ug + i * 4);
            }
            if (pt < 128)
                cpa16(smb + (uint32_t)(DEC_OFF + pt * 4) * 4u, g_decay + pt * 4);
            #pragma unroll
            for (int it = 0; it < 8; ++it) {
                int i = it * 256 + pt;
                cpa16(smb + (uint32_t)(B_OFF0 + i * 4) * 4u, g_bt + i * 4);
            }
            CP_COMMIT();
            #pragma unroll
            for (int it = 0; it < 8; ++it) {
                int i = it * 256 + pt;
                cpa16(smb + (uint32_t)(B_OFF1 + i * 4) * 4u, g_bt + 8192 + i * 4);
            }
            CP_COMMIT();
        }
        CP_WAIT(1);
        BAR_SYNC(1, 256);
        // convert U to tf32 in place
        for (int i = pt * 4; i < 16384; i += 1024) {
            float4 v = *(float4*)&sm[U_OFF + i];
            *(uint4*)&sm[U_OFF + i] = make_uint4(f2tf(v.x), f2tf(v.y), f2tf(v.z), f2tf(v.w));
        }
        BAR_SYNC(1, 256);

        for (int ch = 0; ch < NCH; ++ch) {
            const int bo = (ch & 1) ? B_OFF1 : B_OFF0;
            const int hbase = ch * 64;
            CP_WAIT(1);
            BAR_SYNC(1, 256);  // b(ch) visible to all producer warps

            // ---- L2-prefetch this chunk's X lines (consumed in epilogue) ----
            #pragma unroll
            for (int tm = 0; tm < 2; ++tm) {
                #pragma unroll
                for (int half = 0; half < 2; ++half) {
                    const int mloc = mb1 + tm * 16 + half * 8 + r;
                    const float* xr = X + (size_t)(row0 + mloc) * DH + hbase;
                    #pragma unroll
                    for (int tn = 0; tn < 4; ++tn)
                        pref_l2(xr + nb1 + tn * 8 + 2 * q);
                }
            }

            // ---- GEMM1: acc1 = u[128x128] @ b_chunk[128x64], tile 32x32 ----
            float acc1[2][4][4];
            #pragma unroll
            for (int a = 0; a < 2; ++a)
                #pragma unroll
                for (int b2 = 0; b2 < 4; ++b2)
                    #pragma unroll
                    for (int c2 = 0; c2 < 4; ++c2) acc1[a][b2][c2] = 0.f;
            {
                const uint32_t* su = (const uint32_t*)(sm + U_OFF);
                const uint32_t* sb = (const uint32_t*)(sm + bo);
                #pragma unroll
                for (int ks = 0; ks < 16; ++ks) {
                    const int k0 = ks * 8 + q;
                    uint32_t af[2][4], bf[4][2];
                    #pragma unroll
                    for (int tm = 0; tm < 2; ++tm) {
                        const int m = mb1 + tm * 16 + r;
                        const int kx = (m & 7) << 2;
                        af[tm][0] = su[m * 128 + (k0 ^ kx)];
                        af[tm][1] = su[(m + 8) * 128 + (k0 ^ kx)];
                        af[tm][2] = su[m * 128 + ((k0 + 4) ^ kx)];
                        af[tm][3] = su[(m + 8) * 128 + ((k0 + 4) ^ kx)];
                    }
                    const int nx = (k0 & 3) << 3;
                    #pragma unroll
                    for (int tn = 0; tn < 4; ++tn) {
                        const int n = nb1 + tn * 8 + r;
                        bf[tn][0] = sb[k0 * 64 + (n ^ nx)];
                        bf[tn][1] = sb[(k0 + 4) * 64 + (n ^ nx)];
                    }
                    #pragma unroll
                    for (int tm = 0; tm < 2; ++tm)
                        #pragma unroll
                        for (int tn = 0; tn < 4; ++tn)
                            mma8(acc1[tm][tn], af[tm], bf[tn][0], bf[tn][1]);
                }
            }

            BAR_SYNC(4, 512);  // wait: consumer finished reading xn(ch-1)

            // b(ch) buffer now unreferenced by any producer -> prefetch b(ch+2)
            if (ch + 2 < NCH) {
                #pragma unroll
                for (int it = 0; it < 8; ++it) {
                    int i = it * 256 + pt;
                    cpa16(smb + (uint32_t)(bo + i * 4) * 4u,
                          g_bt + (ch + 2) * 8192 + i * 4);
                }
            }
            CP_COMMIT();

            // ---- epilogue: x_new = acc1 + decay*x ; STG ; stage tf32 xn ----
            {
                const float* dec = sm + DEC_OFF + hbase;
                uint32_t* xs = (uint32_t*)(sm + XN_OFF);
                #pragma unroll
                for (int tm = 0; tm < 2; ++tm) {
                    #pragma unroll
                    for (int half = 0; half < 2; ++half) {
                        const int mloc = mb1 + tm * 16 + half * 8 + r;
                        const size_t grow = (size_t)(row0 + mloc);
                        const float* xr = X + grow * DH + hbase;
                        float* yr = OUT + grow * DH + hbase;
                        const int kx = (mloc & 7) << 2;
                        #pragma unroll
                        for (int tn = 0; tn < 4; ++tn) {
                            const int col = nb1 + tn * 8 + 2 * q;
                            float2 xv = ldg_cs64(xr + col);
                            float2 dv = *(const float2*)(dec + col);
                            float v0 = acc1[tm][tn][half * 2 + 0] + dv.x * xv.x;
                            float v1 = acc1[tm][tn][half * 2 + 1] + dv.y * xv.y;
                            stg_cs64(yr + col, make_float2(v0, v1));
                            *(uint2*)&xs[mloc * 64 + (col ^ kx)] =
                                make_uint2(f2tf(v0), f2tf(v1));
                        }
                    }
                }
            }
            __threadfence_block();
            BAR_ARRIVE(3, 512);  // signal: xn(ch) full
        }
    } else {
        // ===================== CONSUMER (warps 8-15) =====================
        const int ct = tid - 256;  // 0-255
        const int cw = wid - 8;
        const int mb2 = (cw >> 1) * 32, nb2 = (cw & 1) * 64;  // GEMM2 tile 32x64

        // prologue: c0 (group), c1 (group)
        #pragma unroll
        for (int pf = 0; pf < 2; ++pf) {
            const int co = pf ? C_OFF1 : C_OFF0;
            #pragma unroll
            for (int it = 0; it < 8; ++it) {
                int i = it * 256 + ct;
                cpa16(smb + (uint32_t)(co + i * 4) * 4u, g_ct + pf * 8192 + i * 4);
            }
            CP_COMMIT();
        }
        BAR_ARRIVE(4, 512);  // initial: xn empty

        float acc2[2][8][4];
        #pragma unroll
        for (int a = 0; a < 2; ++a)
            #pragma unroll
            for (int b2 = 0; b2 < 8; ++b2)
                #pragma unroll
                for (int c2 = 0; c2 < 4; ++c2) acc2[a][b2][c2] = 0.f;

        for (int ch = 0; ch < NCH; ++ch) {
            const int co = (ch & 1) ? C_OFF1 : C_OFF0;
            CP_WAIT(1);
            BAR_SYNC(2, 256);   // c(ch) visible to all consumer warps
            BAR_SYNC(3, 512);   // wait: xn(ch) full

            // ---- GEMM2: acc2 += x_new_chunk[128x64] @ c_chunk[64x128] ----
            {
                const uint32_t* sx = (const uint32_t*)(sm + XN_OFF);
                const uint32_t* sc = (const uint32_t*)(sm + co);
                #pragma unroll
                for (int ks = 0; ks < 8; ++ks) {
                    const int k0 = ks * 8 + q;
                    uint32_t af[2][4];
                    #pragma unroll
                    for (int tm = 0; tm < 2; ++tm) {
                        const int m = mb2 + tm * 16 + r;
                        const int kx = (m & 7) << 2;
                        af[tm][0] = sx[m * 64 + (k0 ^ kx)];
                        af[tm][1] = sx[(m + 8) * 64 + (k0 ^ kx)];
                        af[tm][2] = sx[m * 64 + ((k0 + 4) ^ kx)];
                        af[tm][3] = sx[(m + 8) * 64 + ((k0 + 4) ^ kx)];
                    }
                    const int nx = (k0 & 3) << 3;
                    #pragma unroll
                    for (int tn = 0; tn < 8; ++tn) {
                        const int n = nb2 + tn * 8 + r;
                        uint32_t b0 = sc[k0 * 128 + (n ^ nx)];
                        uint32_t b1 = sc[(k0 + 4) * 128 + (n ^ nx)];
                        mma8(acc2[0][tn], af[0], b0, b1);
                        mma8(acc2[1][tn], af[1], b0, b1);
                    }
                }
            }
            __threadfence_block();
            BAR_ARRIVE(4, 512);  // signal: xn empty
            BAR_SYNC(2, 256);    // all consumers done reading c(ch)
            if (ch + 2 < NCH) {
                #pragma unroll
                for (int it = 0; it < 8; ++it) {
                    int i = it * 256 + ct;
                    cpa16(smb + (uint32_t)(co + i * 4) * 4u,
                          g_ct + (ch + 2) * 8192 + i * 4);
                }
            }
            CP_COMMIT();
        }

        // ---- final write: Out ----
        float* ob = OUT + (size_t)BATCH * DH;
        #pragma unroll
        for (int tm = 0; tm < 2; ++tm) {
            #pragma unroll
            for (int half = 0; half < 2; ++half) {
                const int mloc = mb2 + tm * 16 + half * 8 + r;
                float* orow = ob + (size_t)(row0 + mloc) * DO;
                #pragma unroll
                for (int tn = 0; tn < 8; ++tn) {
                    const int col = nb2 + tn * 8 + 2 * q;
                    stg_cs64(orow + col,
                             make_float2(acc2[tm][tn][half * 2], acc2[tm][tn][half * 2 + 1]));
                }
            }
        }
    }
}

extern "C" void kernel_launch(void* const* d_in, const int* in_sizes, int n_in,
                              void* d_out, int out_size) {
    const float* x = (const float*)d_in[0];  // [65536, 512]
    const float* u = (const float*)d_in[1];  // [65536, 128]
    const float* a = (const float*)d_in[2];  // [512]
    const float* b = (const float*)d_in[3];  // [128, 512]
    const float* c = (const float*)d_in[4];  // [512, 128]
    float* out = (float*)d_out;

    prep_all<<<64, 512>>>(a, b, c);
    cudaFuncSetAttribute(rnn_kernel, cudaFuncAttributeMaxDynamicSharedMemorySize, SMEM_BYTES);
    rnn_kernel<<<BATCH / BM, NT, SMEM_BYTES>>>(x, u, out);
}

// round 9
// speedup vs baseline: 2.2605x; 2.2605x over previous
#include <cuda_runtime.h>
#include <cuda_fp16.h>
#include <cstdint>

// ---------------------------------------------------------------------------
// fp16 mma.sync (m16n8k16) + ldmatrix kernel, 2 CTAs/SM, family-portable PTX.
// CTA = 64 batch rows, 256 threads, 16 h-chunks of 32, double-buffered b/c.
// fp16 mantissa == tf32 mantissa -> same accuracy, half the tensor instrs.
// SMEM operands are 128B-atomic 8x8 fp16 tiles (conflict-free ldmatrix).
// R8: fixed c-chunk prefetch race (prefetch now after GEMM2 + sync).
// ---------------------------------------------------------------------------

static constexpr int BATCH = 65536;
static constexpr int DH = 512;
static constexpr int DI = 128;
static constexpr int DO = 128;
static constexpr int BM = 64;     // batch rows per CTA
static constexpr int NT = 256;    // 8 warps
static constexpr int NCH = 16;    // h-chunks of 32

// SMEM byte offsets
static constexpr uint32_t XU   = 0;      // U [64m x 128k] fp16 tiles (16384B)
static constexpr uint32_t XB0  = 16384;  // b chunk [128k x 32n] (8192B)
static constexpr uint32_t XB1  = 24576;
static constexpr uint32_t XC0  = 32768;  // c chunk [32k x 128n] (8192B)
static constexpr uint32_t XC1  = 40960;
static constexpr uint32_t XXN  = 49152;  // x_new [64m x 32k] fp16 (4096B)
static constexpr uint32_t XDEC = 53248;  // decay[512] fp32 (2048B)
static constexpr int SMEM_BYTES = 55296;

__device__ float  g_decay[512];
__device__ __half g_bt[65536];  // [16ch][16kt][4nt] 8x8 tiles
__device__ __half g_ct[65536];  // [16ch][4kt][16nt] 8x8 tiles

__device__ __forceinline__ uint32_t smem_u32(const void* p) {
    uint32_t a;
    asm("{ .reg .u64 t; cvta.to.shared.u64 t, %1; cvt.u32.u64 %0, t; }" : "=r"(a) : "l"(p));
    return a;
}
__device__ __forceinline__ void cpa16(uint32_t d, const void* s) {
    asm volatile("cp.async.cg.shared.global [%0], [%1], 16;" :: "r"(d), "l"(s));
}
#define CP_COMMIT() asm volatile("cp.async.commit_group;" ::: "memory")
#define CP_WAIT(n)  asm volatile("cp.async.wait_group %0;" :: "n"(n) : "memory")

#define LDSM4(d, addr) \
    asm volatile("ldmatrix.sync.aligned.m8n8.x4.shared.b16 {%0,%1,%2,%3}, [%4];" \
        : "=r"((d)[0]), "=r"((d)[1]), "=r"((d)[2]), "=r"((d)[3]) : "r"(addr))
#define LDSM4T(d, addr) \
    asm volatile("ldmatrix.sync.aligned.m8n8.x4.trans.shared.b16 {%0,%1,%2,%3}, [%4];" \
        : "=r"((d)[0]), "=r"((d)[1]), "=r"((d)[2]), "=r"((d)[3]) : "r"(addr))

__device__ __forceinline__ void mma16(float* c, const uint32_t* a, uint32_t b0, uint32_t b1) {
    asm volatile(
        "mma.sync.aligned.m16n8k16.row.col.f32.f16.f16.f32 "
        "{%0,%1,%2,%3}, {%4,%5,%6,%7}, {%8,%9}, {%0,%1,%2,%3};"
        : "+f"(c[0]), "+f"(c[1]), "+f"(c[2]), "+f"(c[3])
        : "r"(a[0]), "r"(a[1]), "r"(a[2]), "r"(a[3]), "r"(b0), "r"(b1));
}

// ---------------- prep: softmax + fp16 tile-blocked b/c (one launch) --------
__global__ void prep_all(const float* __restrict__ A, const float* __restrict__ B,
                         const float* __restrict__ C) {
    __shared__ float red[512];
    const int t = threadIdx.x;
    const int idx = blockIdx.x * 512 + t;   // [0, 8192) tile-rows
    {
        const int ch = idx >> 9, rem = idx & 511;
        const int tile = rem >> 3, r8 = rem & 7;
        {   // b: [128k x 512h] -> chunk tiles [kt(16)][nt(4)]
            const int kt = tile >> 2, nt = tile & 3;
            const int k = kt * 8 + r8;
            const float* s = B + (size_t)k * DH + ch * 32 + nt * 8;
            float4 v0 = *(const float4*)s, v1 = *(const float4*)(s + 4);
            __half2* d = (__half2*)(g_bt + ch * 4096 + tile * 64 + r8 * 8);
            d[0] = __floats2half2_rn(v0.x, v0.y);
            d[1] = __floats2half2_rn(v0.z, v0.w);
            d[2] = __floats2half2_rn(v1.x, v1.y);
            d[3] = __floats2half2_rn(v1.z, v1.w);
        }
        {   // c: [512h x 128o] -> chunk tiles [kt(4)][nt(16)]
            const int kt = tile >> 4, nt = tile & 15;
            const int k = kt * 8 + r8;
            const float* s = C + (size_t)(ch * 32 + k) * DO + nt * 8;
            float4 v0 = *(const float4*)s, v1 = *(const float4*)(s + 4);
            __half2* d = (__half2*)(g_ct + ch * 4096 + tile * 64 + r8 * 8);
            d[0] = __floats2half2_rn(v0.x, v0.y);
            d[1] = __floats2half2_rn(v0.z, v0.w);
            d[2] = __floats2half2_rn(v1.x, v1.y);
            d[3] = __floats2half2_rn(v1.z, v1.w);
        }
    }
    if (blockIdx.x == 0) {
        float a = A[t];
        red[t] = a;
        __syncthreads();
        for (int o = 256; o > 0; o >>= 1) {
            if (t < o) red[t] = fmaxf(red[t], red[t + o]);
            __syncthreads();
        }
        float mx = red[0];
        __syncthreads();
        float e = expf(a - mx);
        red[t] = e;
        __syncthreads();
        for (int o = 256; o > 0; o >>= 1) {
            if (t < o) red[t] += red[t + o];
            __syncthreads();
        }
        g_decay[t] = e / red[0];
    }
}

// ------------------------------- main kernel -------------------------------
__global__ void __launch_bounds__(NT, 2)
rnn_kernel(const float* __restrict__ X, const float* __restrict__ U,
           float* __restrict__ OUT) {
    extern __shared__ char smem[];
    const int tid = threadIdx.x, wid = tid >> 5, lane = tid & 31;
    const int q = lane & 3, r = lane >> 2;
    const int row0 = (int)blockIdx.x * BM;
    const uint32_t smb = smem_u32(smem);
    float* decf = (float*)(smem + XDEC);

    // ---- prologue: cp.async decay + b0/c0 (group0), b1/c1 (group1) ----
    if (tid < 128) cpa16(smb + XDEC + tid * 16, g_decay + tid * 4);
    #pragma unroll
    for (int it = 0; it < 2; ++it) {
        int i = it * 256 + tid;
        cpa16(smb + XB0 + i * 16, (const char*)g_bt + i * 16);
        cpa16(smb + XC0 + i * 16, (const char*)g_ct + i * 16);
    }
    CP_COMMIT();
    #pragma unroll
    for (int it = 0; it < 2; ++it) {
        int i = it * 256 + tid;
        cpa16(smb + XB1 + i * 16, (const char*)g_bt + 8192 + i * 16);
        cpa16(smb + XC1 + i * 16, (const char*)g_ct + 8192 + i * 16);
    }
    CP_COMMIT();

    // ---- U [64x128] fp32 -> fp16 tiles in SMEM (kt-swizzled rows) ----
    #pragma unroll
    for (int it = 0; it < 8; ++it) {
        const int widx = it * 8 + wid;            // 0..63
        const int m = (widx & 15) * 4 + (lane >> 3);
        const int k4 = (widx >> 4) * 32 + (lane & 7) * 4;
        float4 v = *(const float4*)(U + (size_t)(row0 + m) * DI + k4);
        uint32_t kt = (uint32_t)(k4 >> 3);
        uint32_t off = XU + ((uint32_t)(m >> 3) << 11) + (kt << 7)
                     + ((((uint32_t)m & 7u) ^ (kt & 7u)) << 4) + ((k4 & 7) << 1);
        *(__half2*)(smem + off)     = __floats2half2_rn(v.x, v.y);
        *(__half2*)(smem + off + 4) = __floats2half2_rn(v.z, v.w);
    }

    // warp tiles
    const int mb1 = (wid >> 1) * 16, nb1 = (wid & 1) * 16;   // GEMM1 16x16
    const int mb2 = (wid >> 2) * 32, nb2 = (wid & 3) * 32;   // GEMM2 32x32

    // GEMM1 A lane geometry (U, swizzled)
    const int lmA1 = mb1 + ((lane >> 3) & 1) * 8 + (lane & 7);
    const uint32_t a1Base = smb + XU + ((uint32_t)(lmA1 >> 3) << 11);
    const uint32_t a1m7 = (uint32_t)(lmA1 & 7);
    const uint32_t a1ktl = (uint32_t)(lane >> 4);
    // GEMM1 B lane geometry (b chunk, plain tiles [kt16][nt4])
    const int lkB1 = (lane & 7) + ((lane >> 3) & 1) * 8;
    const int lnB1 = nb1 + (lane >> 4) * 8;
    const uint32_t b1Off = (uint32_t)(((lkB1 >> 3) * 4 + (lnB1 >> 3)) * 128 + (lkB1 & 7) * 16);
    // GEMM2 A lane geometry (xn, plain tiles [mt8][kt4])
    const int lmA2a = mb2 + ((lane >> 3) & 1) * 8 + (lane & 7);
    const uint32_t a2ktl = (uint32_t)(lane >> 4);
    const uint32_t a2Base0 = smb + XXN + ((uint32_t)(lmA2a >> 3) << 9)
                           + (a2ktl << 7) + (((uint32_t)lmA2a & 7u) << 4);
    const uint32_t a2Base1 = smb + XXN + ((uint32_t)((lmA2a + 16) >> 3) << 9)
                           + (a2ktl << 7) + (((uint32_t)lmA2a & 7u) << 4);
    // GEMM2 B lane geometry (c chunk, plain tiles [kt4][nt16])
    const int lkB2 = (lane & 7) + ((lane >> 3) & 1) * 8;
    const uint32_t b2Row = (uint32_t)((lkB2 >> 3) * 16 * 128 + (lkB2 & 7) * 16);
    const int lnB2a = nb2 + (lane >> 4) * 8;

    float acc2[2][4][4];
    #pragma unroll
    for (int a = 0; a < 2; ++a)
        #pragma unroll
        for (int b = 0; b < 4; ++b)
            #pragma unroll
            for (int c = 0; c < 4; ++c) acc2[a][b][c] = 0.f;

    for (int ch = 0; ch < NCH; ++ch) {
        const uint32_t bo = (ch & 1) ? XB1 : XB0;
        const uint32_t co = (ch & 1) ? XC1 : XC0;
        const int hbase = ch * 32;

        CP_WAIT(1);
        __syncthreads();   // b/c(ch) + (ch==0: U tiles, decay) visible

        // ---- GEMM1: [64x128] @ [128x32] -> acc1 (warp 16x16) ----
        float acc1[2][4] = {{0.f, 0.f, 0.f, 0.f}, {0.f, 0.f, 0.f, 0.f}};
        #pragma unroll
        for (int ks = 0; ks < 8; ++ks) {
            uint32_t kt = a1ktl + 2 * ks;
            uint32_t aA = a1Base + (kt << 7) + ((a1m7 ^ (kt & 7u)) << 4);
            uint32_t af[4], bf[4];
            LDSM4(af, aA);
            LDSM4T(bf, smb + bo + b1Off + ks * 1024);
            mma16(acc1[0], af, bf[0], bf[1]);
            mma16(acc1[1], af, bf[2], bf[3]);
        }

        // ---- epilogue: x_new = acc1 + decay*x ; STG fp32 ; STS fp16 ----
        #pragma unroll
        for (int tn = 0; tn < 2; ++tn) {
            #pragma unroll
            for (int half = 0; half < 2; ++half) {
                const int m = mb1 + half * 8 + r;
                const int col = nb1 + tn * 8 + 2 * q;
                const size_t g = (size_t)(row0 + m) * DH + hbase + col;
                float2 xv = *(const float2*)(X + g);
                float2 dv = *(const float2*)(decf + hbase + col);
                float v0 = acc1[tn][half * 2 + 0] + dv.x * xv.x;
                float v1 = acc1[tn][half * 2 + 1] + dv.y * xv.y;
                *(float2*)(OUT + g) = make_float2(v0, v1);
                *(__half2*)(smem + XXN + ((m >> 3) * 4 + (col >> 3)) * 128
                            + (m & 7) * 16 + (col & 7) * 2) = __floats2half2_rn(v0, v1);
            }
        }
        __syncthreads();   // xn(ch) visible to all warps

        // ---- GEMM2: Out += xn [64x32] @ c [32x128] (warp 32x32) ----
        #pragma unroll
        for (int ks = 0; ks < 2; ++ks) {
            uint32_t a0[4], a1f[4], bf0[4], bf1[4];
            LDSM4(a0, a2Base0 + ks * 256);
            LDSM4(a1f, a2Base1 + ks * 256);
            LDSM4T(bf0, smb + co + b2Row + (uint32_t)((lnB2a >> 3) * 128) + ks * 4096);
            LDSM4T(bf1, smb + co + b2Row + (uint32_t)(((lnB2a + 16) >> 3) * 128) + ks * 4096);
            mma16(acc2[0][0], a0, bf0[0], bf0[1]);
            mma16(acc2[0][1], a0, bf0[2], bf0[3]);
            mma16(acc2[0][2], a0, bf1[0], bf1[1]);
            mma16(acc2[0][3], a0, bf1[2], bf1[3]);
            mma16(acc2[1][0], a1f, bf0[0], bf0[1]);
            mma16(acc2[1][1], a1f, bf0[2], bf0[3]);
            mma16(acc2[1][2], a1f, bf1[0], bf1[1]);
            mma16(acc2[1][3], a1f, bf1[2], bf1[3]);
        }
        __syncthreads();   // all warps done reading b/c(ch) before overwrite

        // ---- prefetch chunk ch+2 into the buffers just freed ----
        if (ch + 2 < NCH) {
            #pragma unroll
            for (int it = 0; it < 2; ++it) {
                int i = it * 256 + tid;
                cpa16(smb + bo + i * 16, (const char*)g_bt + (ch + 2) * 8192 + i * 16);
                cpa16(smb + co + i * 16, (const char*)g_ct + (ch + 2) * 8192 + i * 16);
            }
        }
        CP_COMMIT();  // exactly one group per iteration keeps the ledger uniform
    }

    // ---- final write: output GEMM ----
    float* ob = OUT + (size_t)BATCH * DH;
    #pragma unroll
    for (int mt = 0; mt < 2; ++mt) {
        #pragma unroll
        for (int half = 0; half < 2; ++half) {
            const int m = mb2 + mt * 16 + half * 8 + r;
            float* orow = ob + (size_t)(row0 + m) * DO;
            #pragma unroll
            for (int nt8 = 0; nt8 < 4; ++nt8) {
                const int col = nb2 + nt8 * 8 + 2 * q;
                *(float2*)(orow + col) =
                    make_float2(acc2[mt][nt8][half * 2], acc2[mt][nt8][half * 2 + 1]);
            }
        }
    }
}

extern "C" void kernel_launch(void* const* d_in, const int* in_sizes, int n_in,
                              void* d_out, int out_size) {
    const float* x = (const float*)d_in[0];  // [65536, 512]
    const float* u = (const float*)d_in[1];  // [65536, 128]
    const float* a = (const float*)d_in[2];  // [512]
    const float* b = (const float*)d_in[3];  // [128, 512]
    const float* c = (const float*)d_in[4];  // [512, 128]
    float* out = (float*)d_out;

    prep_all<<<16, 512>>>(a, b, c);
    cudaFuncSetAttribute(rnn_kernel, cudaFuncAttributeMaxDynamicSharedMemorySize, SMEM_BYTES);
    rnn_kernel<<<BATCH / BM, NT, SMEM_BYTES>>>(x, u, out);
}

// round 12
// speedup vs baseline: 2.3630x; 1.0454x over previous
#include <cuda_runtime.h>
#include <cuda_fp16.h>
#include <cstdint>

// ---------------------------------------------------------------------------
// fp16 mma.sync (m16n8k16) + ldmatrix, 2 CTAs/SM, family-portable PTX.
// R11 = R10 + fix: prologue chunk-1 cp.async source offset (8192 -> 16384 B).
// 8 h-chunks of 64; GEMM1 warp tile 32x16 (B redundancy x2), GEMM2 32x32.
// ---------------------------------------------------------------------------

static constexpr int BATCH = 65536;
static constexpr int DH = 512;
static constexpr int DI = 128;
static constexpr int DO = 128;
static constexpr int BM = 64;     // batch rows per CTA
static constexpr int NT = 256;    // 8 warps
static constexpr int NCH = 8;     // h-chunks of 64

// SMEM byte offsets
static constexpr uint32_t XU   = 0;      // U [64m x 128k] fp16 tiles (16384B)
static constexpr uint32_t XB0  = 16384;  // b chunk [128k x 64n] (16384B)
static constexpr uint32_t XB1  = 32768;
static constexpr uint32_t XC0  = 49152;  // c chunk [64k x 128n] (16384B)
static constexpr uint32_t XC1  = 65536;
static constexpr uint32_t XXN  = 81920;  // x_new [64m x 64k] fp16 (8192B)
static constexpr uint32_t XDEC = 90112;  // decay[512] fp32 (2048B)
static constexpr int SMEM_BYTES = 92160;

static constexpr int CHB = 16384;  // bytes per b/c chunk in gmem staging

__device__ float  g_decay[512];
__device__ __half g_bt[65536];  // [8ch][16kt][8nt] 8x8 tiles
__device__ __half g_ct[65536];  // [8ch][8kt][16nt] 8x8 tiles

__device__ __forceinline__ uint32_t smem_u32(const void* p) {
    uint32_t a;
    asm("{ .reg .u64 t; cvta.to.shared.u64 t, %1; cvt.u32.u64 %0, t; }" : "=r"(a) : "l"(p));
    return a;
}
__device__ __forceinline__ void cpa16(uint32_t d, const void* s) {
    asm volatile("cp.async.cg.shared.global [%0], [%1], 16;" :: "r"(d), "l"(s));
}
#define CP_COMMIT() asm volatile("cp.async.commit_group;" ::: "memory")
#define CP_WAIT(n)  asm volatile("cp.async.wait_group %0;" :: "n"(n) : "memory")

#define LDSM4(d, addr) \
    asm volatile("ldmatrix.sync.aligned.m8n8.x4.shared.b16 {%0,%1,%2,%3}, [%4];" \
        : "=r"((d)[0]), "=r"((d)[1]), "=r"((d)[2]), "=r"((d)[3]) : "r"(addr))
#define LDSM4T(d, addr) \
    asm volatile("ldmatrix.sync.aligned.m8n8.x4.trans.shared.b16 {%0,%1,%2,%3}, [%4];" \
        : "=r"((d)[0]), "=r"((d)[1]), "=r"((d)[2]), "=r"((d)[3]) : "r"(addr))

__device__ __forceinline__ void mma16(float* c, const uint32_t* a, uint32_t b0, uint32_t b1) {
    asm volatile(
        "mma.sync.aligned.m16n8k16.row.col.f32.f16.f16.f32 "
        "{%0,%1,%2,%3}, {%4,%5,%6,%7}, {%8,%9}, {%0,%1,%2,%3};"
        : "+f"(c[0]), "+f"(c[1]), "+f"(c[2]), "+f"(c[3])
        : "r"(a[0]), "r"(a[1]), "r"(a[2]), "r"(a[3]), "r"(b0), "r"(b1));
}

// ---------------- prep: softmax + fp16 tile-blocked b/c (one launch) --------
__global__ void prep_all(const float* __restrict__ A, const float* __restrict__ B,
                         const float* __restrict__ C) {
    __shared__ float red[512];
    const int t = threadIdx.x;
    const int idx = blockIdx.x * 512 + t;   // [0, 8192) tile-rows
    {
        const int ch = idx >> 10, rem = idx & 1023;
        const int tile = rem >> 3, r8 = rem & 7;
        {   // b chunk [128k x 64n] -> tiles [kt(16)][nt(8)]
            const int kt = tile >> 3, nt = tile & 7;
            const int k = kt * 8 + r8;
            const float* s = B + (size_t)k * DH + ch * 64 + nt * 8;
            float4 v0 = *(const float4*)s, v1 = *(const float4*)(s + 4);
            __half2* d = (__half2*)(g_bt + ch * 8192 + tile * 64 + r8 * 8);
            d[0] = __floats2half2_rn(v0.x, v0.y);
            d[1] = __floats2half2_rn(v0.z, v0.w);
            d[2] = __floats2half2_rn(v1.x, v1.y);
            d[3] = __floats2half2_rn(v1.z, v1.w);
        }
        {   // c chunk [64k x 128n] -> tiles [kt(8)][nt(16)]
            const int kt = tile >> 4, nt = tile & 15;
            const int k = kt * 8 + r8;
            const float* s = C + (size_t)(ch * 64 + k) * DO + nt * 8;
            float4 v0 = *(const float4*)s, v1 = *(const float4*)(s + 4);
            __half2* d = (__half2*)(g_ct + ch * 8192 + tile * 64 + r8 * 8);
            d[0] = __floats2half2_rn(v0.x, v0.y);
            d[1] = __floats2half2_rn(v0.z, v0.w);
            d[2] = __floats2half2_rn(v1.x, v1.y);
            d[3] = __floats2half2_rn(v1.z, v1.w);
        }
    }
    if (blockIdx.x == 0) {
        float a = A[t];
        red[t] = a;
        __syncthreads();
        for (int o = 256; o > 0; o >>= 1) {
            if (t < o) red[t] = fmaxf(red[t], red[t + o]);
            __syncthreads();
        }
        float mx = red[0];
        __syncthreads();
        float e = expf(a - mx);
        red[t] = e;
        __syncthreads();
        for (int o = 256; o > 0; o >>= 1) {
            if (t < o) red[t] += red[t + o];
            __syncthreads();
        }
        g_decay[t] = e / red[0];
    }
}

// ------------------------------- main kernel -------------------------------
__global__ void __launch_bounds__(NT, 2)
rnn_kernel(const float* __restrict__ X, const float* __restrict__ U,
           float* __restrict__ OUT) {
    extern __shared__ char smem[];
    const int tid = threadIdx.x, wid = tid >> 5, lane = tid & 31;
    const int q = lane & 3, r = lane >> 2;
    const int row0 = (int)blockIdx.x * BM;
    const uint32_t smb = smem_u32(smem);
    float* decf = (float*)(smem + XDEC);

    // ---- prologue: cp.async decay + b0/c0 (group0), b1/c1 (group1) ----
    if (tid < 128) cpa16(smb + XDEC + tid * 16, g_decay + tid * 4);
    #pragma unroll
    for (int it = 0; it < 4; ++it) {
        int i = it * 256 + tid;
        cpa16(smb + XB0 + i * 16, (const char*)g_bt + i * 16);
        cpa16(smb + XC0 + i * 16, (const char*)g_ct + i * 16);
    }
    CP_COMMIT();
    #pragma unroll
    for (int it = 0; it < 4; ++it) {
        int i = it * 256 + tid;
        cpa16(smb + XB1 + i * 16, (const char*)g_bt + CHB + i * 16);
        cpa16(smb + XC1 + i * 16, (const char*)g_ct + CHB + i * 16);
    }
    CP_COMMIT();

    // ---- U [64x128] fp32 -> fp16 tiles in SMEM (kt-swizzled rows) ----
    #pragma unroll
    for (int it = 0; it < 8; ++it) {
        const int widx = it * 8 + wid;            // 0..63
        const int m = (widx & 15) * 4 + (lane >> 3);
        const int k4 = (widx >> 4) * 32 + (lane & 7) * 4;
        float4 v = *(const float4*)(U + (size_t)(row0 + m) * DI + k4);
        uint32_t kt = (uint32_t)(k4 >> 3);
        uint32_t off = XU + ((uint32_t)(m >> 3) << 11) + (kt << 7)
                     + ((((uint32_t)m & 7u) ^ (kt & 7u)) << 4) + ((k4 & 7) << 1);
        *(__half2*)(smem + off)     = __floats2half2_rn(v.x, v.y);
        *(__half2*)(smem + off + 4) = __floats2half2_rn(v.z, v.w);
    }

    // warp tiles
    const int mb1 = (wid >> 2) * 32, nb1 = (wid & 3) * 16;   // GEMM1 32x16
    const int mb2 = (wid >> 2) * 32, nb2 = (wid & 3) * 32;   // GEMM2 32x32

    // GEMM1 A lane geometry (U, swizzled), two m16 tiles
    const int a1m0 = mb1 + (lane & 15);
    const int a1m1 = a1m0 + 16;
    const uint32_t a1rb0 = XU + ((uint32_t)(a1m0 >> 3) << 11);
    const uint32_t a1rb1 = XU + ((uint32_t)(a1m1 >> 3) << 11);
    const uint32_t a1m70 = (uint32_t)(a1m0 & 7), a1m71 = (uint32_t)(a1m1 & 7);
    const uint32_t ktl = (uint32_t)(lane >> 4);
    // GEMM1 B lane geometry (b chunk tiles [kt16][nt8])
    const int lkB1 = (lane & 7) + ((lane >> 3) & 1) * 8;
    const uint32_t b1Off = (uint32_t)(((lkB1 >> 3) * 8 + ((nb1 + (lane >> 4) * 8) >> 3)) * 128
                                      + (lkB1 & 7) * 16);
    // GEMM2 A lane geometry (xn tiles [mt8][kt8]), two m16 tiles
    const int a2m0 = mb2 + (lane & 15);
    const int a2m1 = a2m0 + 16;
    const uint32_t a2b0 = XXN + (uint32_t)(((a2m0 >> 3) * 8 + (int)ktl) * 128 + (a2m0 & 7) * 16);
    const uint32_t a2b1 = XXN + (uint32_t)(((a2m1 >> 3) * 8 + (int)ktl) * 128 + (a2m1 & 7) * 16);
    // GEMM2 B lane geometry (c chunk tiles [kt8][nt16]), two n16 tiles
    const int lkB2 = (lane & 7) + ((lane >> 3) & 1) * 8;
    const uint32_t b2b0 = (uint32_t)(((lkB2 >> 3) * 16 + ((nb2 + (lane >> 4) * 8) >> 3)) * 128
                                     + (lkB2 & 7) * 16);
    const uint32_t b2b1 = b2b0 + 256;  // +16 n-cols = +2 tiles

    float acc2[2][4][4];
    #pragma unroll
    for (int a = 0; a < 2; ++a)
        #pragma unroll
        for (int b = 0; b < 4; ++b)
            #pragma unroll
            for (int c = 0; c < 4; ++c) acc2[a][b][c] = 0.f;

    for (int ch = 0; ch < NCH; ++ch) {
        const uint32_t bo = (ch & 1) ? XB1 : XB0;
        const uint32_t co = (ch & 1) ? XC1 : XC0;
        const int hbase = ch * 64;

        CP_WAIT(1);
        __syncthreads();   // b/c(ch) + (ch==0: U tiles, decay) visible

        // ---- GEMM1: [64x128] @ [128x64] -> acc1 (warp 32x16) ----
        float acc1[2][2][4];
        #pragma unroll
        for (int a = 0; a < 2; ++a)
            #pragma unroll
            for (int b = 0; b < 2; ++b)
                #pragma unroll
                for (int c = 0; c < 4; ++c) acc1[a][b][c] = 0.f;
        #pragma unroll
        for (int ks = 0; ks < 8; ++ks) {
            uint32_t kt = ktl + 2 * ks;
            uint32_t af0[4], af1[4], bf[4];
            LDSM4(af0, smb + a1rb0 + (kt << 7) + ((a1m70 ^ (kt & 7u)) << 4));
            LDSM4(af1, smb + a1rb1 + (kt << 7) + ((a1m71 ^ (kt & 7u)) << 4));
            LDSM4T(bf, smb + bo + b1Off + ks * 2048);
            mma16(acc1[0][0], af0, bf[0], bf[1]);
            mma16(acc1[0][1], af0, bf[2], bf[3]);
            mma16(acc1[1][0], af1, bf[0], bf[1]);
            mma16(acc1[1][1], af1, bf[2], bf[3]);
        }

        // ---- epilogue: x_new = acc1 + decay*x ; STG fp32 ; STS fp16 ----
        #pragma unroll
        for (int mt = 0; mt < 2; ++mt) {
            #pragma unroll
            for (int nt = 0; nt < 2; ++nt) {
                #pragma unroll
                for (int half = 0; half < 2; ++half) {
                    const int m = mb1 + mt * 16 + half * 8 + r;
                    const int col = nb1 + nt * 8 + 2 * q;
                    const size_t g = (size_t)(row0 + m) * DH + hbase + col;
                    float2 xv = *(const float2*)(X + g);
                    float2 dv = *(const float2*)(decf + hbase + col);
                    float v0 = acc1[mt][nt][half * 2 + 0] + dv.x * xv.x;
                    float v1 = acc1[mt][nt][half * 2 + 1] + dv.y * xv.y;
                    *(float2*)(OUT + g) = make_float2(v0, v1);
                    *(__half2*)(smem + XXN + ((m >> 3) * 8 + (col >> 3)) * 128
                                + (m & 7) * 16 + (col & 7) * 2) = __floats2half2_rn(v0, v1);
                }
            }
        }
        __syncthreads();   // xn(ch) visible to all warps

        // ---- GEMM2: Out += xn [64x64] @ c [64x128] (warp 32x32) ----
        #pragma unroll
        for (int ks = 0; ks < 4; ++ks) {
            uint32_t a0[4], a1f[4], bf0[4], bf1[4];
            LDSM4(a0, smb + a2b0 + ks * 256);
            LDSM4(a1f, smb + a2b1 + ks * 256);
            LDSM4T(bf0, smb + co + b2b0 + ks * 4096);
            LDSM4T(bf1, smb + co + b2b1 + ks * 4096);
            mma16(acc2[0][0], a0, bf0[0], bf0[1]);
            mma16(acc2[0][1], a0, bf0[2], bf0[3]);
            mma16(acc2[0][2], a0, bf1[0], bf1[1]);
            mma16(acc2[0][3], a0, bf1[2], bf1[3]);
            mma16(acc2[1][0], a1f, bf0[0], bf0[1]);
            mma16(acc2[1][1], a1f, bf0[2], bf0[3]);
            mma16(acc2[1][2], a1f, bf1[0], bf1[1]);
            mma16(acc2[1][3], a1f, bf1[2], bf1[3]);
        }
        __syncthreads();   // all warps done reading b/c(ch) before overwrite

        // ---- prefetch chunk ch+2 into the buffers just freed ----
        if (ch + 2 < NCH) {
            #pragma unroll
            for (int it = 0; it < 4; ++it) {
                int i = it * 256 + tid;
                cpa16(smb + bo + i * 16, (const char*)g_bt + (ch + 2) * CHB + i * 16);
                cpa16(smb + co + i * 16, (const char*)g_ct + (ch + 2) * CHB + i * 16);
            }
        }
        CP_COMMIT();  // exactly one group per iteration keeps the ledger uniform
    }

    // ---- final write: output GEMM ----
    float* ob = OUT + (size_t)BATCH * DH;
    #pragma unroll
    for (int mt = 0; mt < 2; ++mt) {
        #pragma unroll
        for (int half = 0; half < 2; ++half) {
            const int m = mb2 + mt * 16 + half * 8 + r;
            float* orow = ob + (size_t)(row0 + m) * DO;
            #pragma unroll
            for (int nt8 = 0; nt8 < 4; ++nt8) {
                const int col = nb2 + nt8 * 8 + 2 * q;
                *(float2*)(orow + col) =
                    make_float2(acc2[mt][nt8][half * 2], acc2[mt][nt8][half * 2 + 1]);
            }
        }
    }
}

extern "C" void kernel_launch(void* const* d_in, const int* in_sizes, int n_in,
                              void* d_out, int out_size) {
    const float* x = (const float*)d_in[0];  // [65536, 512]
    const float* u = (const float*)d_in[1];  // [65536, 128]
    const float* a = (const float*)d_in[2];  // [512]
    const float* b = (const float*)d_in[3];  // [128, 512]
    const float* c = (const float*)d_in[4];  // [512, 128]
    float* out = (float*)d_out;

    prep_all<<<16, 512>>>(a, b, c);
    cudaFuncSetAttribute(rnn_kernel, cudaFuncAttributeMaxDynamicSharedMemorySize, SMEM_BYTES);
    rnn_kernel<<<BATCH / BM, NT, SMEM_BYTES>>>(x, u, out);
}